// round 16
// baseline (speedup 1.0000x reference)
#include <cuda_runtime.h>

#define SEQ   600
#define PP    6
#define KD    7
#define NW    8      // warps (rows) per block
#define CH    19     // contiguous u-chunk per lane (19*32 = 608 >= 600)
#define ROWPADF 612  // row pitch in floats: 612 % 32 == 4 -> conflict-free cross-row LDS

// lower-triangular index, r >= c
#define LT(r, c) ((r) * ((r) + 1) / 2 + (c))

__device__ __forceinline__ float frsqrt_fast(float v) {
    float r;
    asm("rsqrt.approx.f32 %0, %1;" : "=f"(r) : "f"(v));
    return r;
}

__global__ __launch_bounds__(NW * 32, 6)
void ar_warp(const float* __restrict__ x, float* __restrict__ out, int N) {
    __shared__ float sh[NW][ROWPADF];
    __shared__ float sbuf[NW][8];    // C0..C6, S per row
    __shared__ float wbuf[NW][8];    // solved w0..w6 per row
    __shared__ float Ash[NW][29];    // Cholesky workspace (29*r % 32 distinct -> no conflicts)

    const int warp = threadIdx.x >> 5;
    const int lane = threadIdx.x & 31;
    const int row  = blockIdx.x * NW + warp;
    const bool active = (row < N);

    // ================= Phase 1: load + autocorr + reduce (warp per row) ====
    if (active) {
        const float4* xv = (const float4*)(x + (size_t)row * SEQ);
        float4* sv = (float4*)sh[warp];
        #pragma unroll
        for (int i = 0; i < 5; i++) {
            int j = lane + i * 32;
            if (j < 150) sv[j] = xv[j];
        }
        __syncwarp();
        const float* s = sh[warp];

        float C[7] = {0.f, 0.f, 0.f, 0.f, 0.f, 0.f, 0.f};
        float S = 0.f;
        const int u0 = lane * CH;
        float r6[6];   // x[u-6..u-1]
        #pragma unroll
        for (int i = 0; i < 6; i++) {
            int idx = u0 - 6 + i;
            r6[i] = (idx >= 0) ? s[idx] : 0.f;
        }
        #pragma unroll
        for (int i = 0; i < CH; i++) {
            const int u = u0 + i;
            if (u < SEQ) {
                const float v = s[u];
                S += v;
                C[0] = fmaf(v, v,     C[0]);
                C[1] = fmaf(v, r6[5], C[1]);
                C[2] = fmaf(v, r6[4], C[2]);
                C[3] = fmaf(v, r6[3], C[3]);
                C[4] = fmaf(v, r6[2], C[4]);
                C[5] = fmaf(v, r6[1], C[5]);
                C[6] = fmaf(v, r6[0], C[6]);
                r6[0] = r6[1]; r6[1] = r6[2]; r6[2] = r6[3];
                r6[3] = r6[4]; r6[4] = r6[5]; r6[5] = v;
            }
        }

        #pragma unroll
        for (int j = 0; j < 7; j++) {
            #pragma unroll
            for (int o = 16; o > 0; o >>= 1)
                C[j] += __shfl_xor_sync(0xffffffffu, C[j], o);
        }
        #pragma unroll
        for (int o = 16; o > 0; o >>= 1)
            S += __shfl_xor_sync(0xffffffffu, S, o);

        if (lane == 0) {
            #pragma unroll
            for (int j = 0; j < 7; j++) sbuf[warp][j] = C[j];
            sbuf[warp][7] = S;
        }
    }
    __syncthreads();

    // ========== Phase 2: warp 0, lanes 0..7 solve one row each (lockstep) ==
    if (warp == 0 && lane < NW) {
        const int r = lane;
        const int rrow = blockIdx.x * NW + r;
        if (rrow < N) {
            const float* sr = sh[r];
            float cc[7];
            #pragma unroll
            for (int j = 0; j < 7; j++) cc[j] = sbuf[r][j];
            const float S = sbuf[r][7];

            float* A = Ash[r];       // shared workspace keeps reg peak low
            float B[KD];
            A[LT(0, 0)] = 594.f;
            #pragma unroll
            for (int a = 0; a < 6; a++) {
                float hs = 0.f, ts = 0.f;
                #pragma unroll
                for (int u = 0; u <= 4; u++) if (u <= 4 - a) hs += sr[u];
                #pragma unroll
                for (int i = 0; i <= 5; i++) if (i <= a) ts += sr[594 + 5 - a + i];
                A[LT(1 + a, 0)] = S - hs - ts;
            }
            #pragma unroll
            for (int a = 0; a < 6; a++) {
                #pragma unroll
                for (int b = 0; b <= a; b++) {
                    float hs = 0.f, ts = 0.f;
                    #pragma unroll
                    for (int u = 0; u <= 4; u++)
                        if (u <= 4 - a) hs = fmaf(sr[u], sr[u + a - b], hs);
                    #pragma unroll
                    for (int i = 0; i <= 5; i++)
                        if (i <= b) ts = fmaf(sr[594 + 5 - a + i], sr[594 + 5 - b + i], ts);
                    A[LT(1 + a, 1 + b)] = cc[a - b] - hs - ts;
                }
            }
            B[0] = S - (sr[0] + sr[1] + sr[2] + sr[3] + sr[4] + sr[5]);
            #pragma unroll
            for (int a = 0; a < 6; a++) {
                float hs = 0.f;
                #pragma unroll
                for (int u = 0; u <= 4; u++)
                    if (u <= 4 - a) hs = fmaf(sr[u], sr[u + a + 1], hs);
                B[1 + a] = cc[a + 1] - hs;
            }

            // Cholesky via rsqrt: diagonal slot holds inv = 1/L[c][c].
            #pragma unroll
            for (int c = 0; c < KD; c++) {
                float sd = A[LT(c, c)];
                #pragma unroll
                for (int k = 0; k < c; k++) {
                    float lck = A[LT(c, k)];
                    sd = fmaf(-lck, lck, sd);
                }
                const float inv = frsqrt_fast(sd);
                A[LT(c, c)] = inv;
                #pragma unroll
                for (int rr = c + 1; rr < KD; rr++) {
                    float s2 = A[LT(rr, c)];
                    #pragma unroll
                    for (int k = 0; k < c; k++) s2 = fmaf(-A[LT(rr, k)], A[LT(c, k)], s2);
                    A[LT(rr, c)] = s2 * inv;
                }
            }
            // Forward solve L z = b (diag slot = inv)
            #pragma unroll
            for (int rr = 0; rr < KD; rr++) {
                float s2 = B[rr];
                #pragma unroll
                for (int k = 0; k < rr; k++) s2 = fmaf(-A[LT(rr, k)], B[k], s2);
                B[rr] = s2 * A[LT(rr, rr)];
            }
            // Back solve L^T w = z
            #pragma unroll
            for (int c = KD - 1; c >= 0; c--) {
                float s2 = B[c];
                #pragma unroll
                for (int k = c + 1; k < KD; k++) s2 = fmaf(-A[LT(k, c)], B[k], s2);
                B[c] = s2 * A[LT(c, c)];
            }
            #pragma unroll
            for (int k = 0; k < KD; k++) wbuf[r][k] = B[k];
        }
    }
    __syncthreads();

    // ================= Phase 3: emit (warp per row) =========================
    if (!active) return;
    const float* s = sh[warp];
    const float w0 = wbuf[warp][0], w1 = wbuf[warp][1], w2 = wbuf[warp][2],
                w3 = wbuf[warp][3], w4 = wbuf[warp][4], w5 = wbuf[warp][5],
                w6 = wbuf[warp][6];

    const size_t Ns = (size_t)N;
    float* coeffs = out;
    float* plog   = out + Ns * 3600;
    int*   phard  = (int*)(out + Ns * 3605);
    float* xhat   = out + Ns * 3606;

    // ---- coeffs: repeating [w1..w6] pattern over float4 (period 3) ----
    const float4 p0 = make_float4(w1, w2, w3, w4);
    const float4 p1 = make_float4(w5, w6, w1, w2);
    const float4 p2 = make_float4(w3, w4, w5, w6);
    const int m0 = lane % 3;
    const float4 q0 = (m0 == 0) ? p0 : ((m0 == 1) ? p1 : p2);  // c = 0
    const float4 q1 = (m0 == 0) ? p1 : ((m0 == 1) ? p2 : p0);  // c = 1
    const float4 q2 = (m0 == 0) ? p2 : ((m0 == 1) ? p0 : p1);  // c = 2

    float4* cv = (float4*)(coeffs + (size_t)row * 3600);
    {
        const float4 z4 = make_float4(0.f, 0.f, 0.f, 0.f);
        cv[lane] = (lane < 9) ? z4 : q0;
    }
    #pragma unroll
    for (int k = 1; k < 28; k++) {
        const int c = (2 * k) % 3;                // compile-time
        const float4 v = (c == 0) ? q0 : ((c == 1) ? q1 : q2);
        cv[lane + 32 * k] = v;
    }
    if (lane < 4) cv[lane + 896] = q2;           // tail, c = 2

    // ---- p_logits / p_hard: zeros ----
    if (lane < 5) plog[(size_t)row * 5 + lane] = 0.f;
    if (lane == 5) phard[row] = 0;

    // ---- x_hat: 0 for t<6, else w0 + sum w[k]*x[t-k] ----
    float4* hv = (float4*)(xhat + (size_t)row * SEQ);
    #pragma unroll
    for (int k = 0; k < 5; k++) {
        const int i = lane + k * 32;
        if (k < 4 || lane < 22) {                 // 150 = 4*32 + 22
            float4 v;
            float* vc = (float*)&v;
            const int t0 = i * 4;
            #pragma unroll
            for (int c = 0; c < 4; c++) {
                const int t = t0 + c;
                float p = 0.f;
                if (t >= PP) {
                    p = w0;
                    p = fmaf(w1, s[t - 1], p);
                    p = fmaf(w2, s[t - 2], p);
                    p = fmaf(w3, s[t - 3], p);
                    p = fmaf(w4, s[t - 4], p);
                    p = fmaf(w5, s[t - 5], p);
                    p = fmaf(w6, s[t - 6], p);
                }
                vc[c] = p;
            }
            hv[i] = v;
        }
    }
}

extern "C" void kernel_launch(void* const* d_in, const int* in_sizes, int n_in,
                              void* d_out, int out_size) {
    const float* x = (const float*)d_in[0];
    const int N = in_sizes[0] / SEQ;
    float* out = (float*)d_out;
    const int blocks = (N + NW - 1) / NW;
    ar_warp<<<blocks, NW * 32>>>(x, out, N);
}

// round 17
// speedup vs baseline: 1.0236x; 1.0236x over previous
#include <cuda_runtime.h>

#define SEQ   600
#define PP    6
#define KD    7
#define NW    8      // warps (rows) per block
#define CH    19     // contiguous u-chunk per lane (19*32 = 608 >= 600)
#define ROWPADF 612  // row pitch in floats: 612 % 32 == 4 -> conflict-free cross-row LDS

// lower-triangular index, r >= c
#define LT(r, c) ((r) * ((r) + 1) / 2 + (c))

__device__ __forceinline__ float frsqrt_fast(float v) {
    float r;
    asm("rsqrt.approx.f32 %0, %1;" : "=f"(r) : "f"(v));
    return r;
}

__global__ __launch_bounds__(NW * 32, 6)
void ar_warp(const float* __restrict__ x, float* __restrict__ out, int N) {
    __shared__ float sh[NW][ROWPADF];
    __shared__ float sbuf[NW][8];    // C0..C6, S per row
    __shared__ float wbuf[NW][8];    // solved w0..w6 per row
    __shared__ float Ash[NW][29];    // Cholesky workspace (29*r % 32 distinct -> no conflicts)

    const int warp = threadIdx.x >> 5;
    const int lane = threadIdx.x & 31;
    const int row  = blockIdx.x * NW + warp;
    const bool active = (row < N);

    // ================= Phase 1: load + autocorr + reduce (warp per row) ====
    if (active) {
        const float4* xv = (const float4*)(x + (size_t)row * SEQ);
        float4* sv = (float4*)sh[warp];
        #pragma unroll
        for (int i = 0; i < 5; i++) {
            int j = lane + i * 32;
            if (j < 150) sv[j] = xv[j];
        }
        __syncwarp();
        const float* s = sh[warp];

        float C[7] = {0.f, 0.f, 0.f, 0.f, 0.f, 0.f, 0.f};
        float S = 0.f;
        const int u0 = lane * CH;
        float r6[6];   // x[u-6..u-1]
        #pragma unroll
        for (int i = 0; i < 6; i++) {
            int idx = u0 - 6 + i;
            r6[i] = (idx >= 0) ? s[idx] : 0.f;
        }
        #pragma unroll
        for (int i = 0; i < CH; i++) {
            const int u = u0 + i;
            if (u < SEQ) {
                const float v = s[u];
                S += v;
                C[0] = fmaf(v, v,     C[0]);
                C[1] = fmaf(v, r6[5], C[1]);
                C[2] = fmaf(v, r6[4], C[2]);
                C[3] = fmaf(v, r6[3], C[3]);
                C[4] = fmaf(v, r6[2], C[4]);
                C[5] = fmaf(v, r6[1], C[5]);
                C[6] = fmaf(v, r6[0], C[6]);
                r6[0] = r6[1]; r6[1] = r6[2]; r6[2] = r6[3];
                r6[3] = r6[4]; r6[4] = r6[5]; r6[5] = v;
            }
        }

        #pragma unroll
        for (int j = 0; j < 7; j++) {
            #pragma unroll
            for (int o = 16; o > 0; o >>= 1)
                C[j] += __shfl_xor_sync(0xffffffffu, C[j], o);
        }
        #pragma unroll
        for (int o = 16; o > 0; o >>= 1)
            S += __shfl_xor_sync(0xffffffffu, S, o);

        if (lane == 0) {
            #pragma unroll
            for (int j = 0; j < 7; j++) sbuf[warp][j] = C[j];
            sbuf[warp][7] = S;
        }
    }
    __syncthreads();

    // ========== Phase 2: warp 0, lanes 0..7 solve one row each (lockstep) ==
    if (warp == 0 && lane < NW) {
        const int r = lane;
        const int rrow = blockIdx.x * NW + r;
        if (rrow < N) {
            const float* sr = sh[r];
            float cc[7];
            #pragma unroll
            for (int j = 0; j < 7; j++) cc[j] = sbuf[r][j];
            const float S = sbuf[r][7];

            float* A = Ash[r];       // shared workspace keeps reg peak low
            float B[KD];
            A[LT(0, 0)] = 594.f;
            #pragma unroll
            for (int a = 0; a < 6; a++) {
                float hs = 0.f, ts = 0.f;
                #pragma unroll
                for (int u = 0; u <= 4; u++) if (u <= 4 - a) hs += sr[u];
                #pragma unroll
                for (int i = 0; i <= 5; i++) if (i <= a) ts += sr[594 + 5 - a + i];
                A[LT(1 + a, 0)] = S - hs - ts;
            }
            #pragma unroll
            for (int a = 0; a < 6; a++) {
                #pragma unroll
                for (int b = 0; b <= a; b++) {
                    float hs = 0.f, ts = 0.f;
                    #pragma unroll
                    for (int u = 0; u <= 4; u++)
                        if (u <= 4 - a) hs = fmaf(sr[u], sr[u + a - b], hs);
                    #pragma unroll
                    for (int i = 0; i <= 5; i++)
                        if (i <= b) ts = fmaf(sr[594 + 5 - a + i], sr[594 + 5 - b + i], ts);
                    A[LT(1 + a, 1 + b)] = cc[a - b] - hs - ts;
                }
            }
            B[0] = S - (sr[0] + sr[1] + sr[2] + sr[3] + sr[4] + sr[5]);
            #pragma unroll
            for (int a = 0; a < 6; a++) {
                float hs = 0.f;
                #pragma unroll
                for (int u = 0; u <= 4; u++)
                    if (u <= 4 - a) hs = fmaf(sr[u], sr[u + a + 1], hs);
                B[1 + a] = cc[a + 1] - hs;
            }

            // Cholesky via rsqrt: diagonal slot holds inv = 1/L[c][c].
            #pragma unroll
            for (int c = 0; c < KD; c++) {
                float sd = A[LT(c, c)];
                #pragma unroll
                for (int k = 0; k < c; k++) {
                    float lck = A[LT(c, k)];
                    sd = fmaf(-lck, lck, sd);
                }
                const float inv = frsqrt_fast(sd);
                A[LT(c, c)] = inv;
                #pragma unroll
                for (int rr = c + 1; rr < KD; rr++) {
                    float s2 = A[LT(rr, c)];
                    #pragma unroll
                    for (int k = 0; k < c; k++) s2 = fmaf(-A[LT(rr, k)], A[LT(c, k)], s2);
                    A[LT(rr, c)] = s2 * inv;
                }
            }
            // Forward solve L z = b (diag slot = inv)
            #pragma unroll
            for (int rr = 0; rr < KD; rr++) {
                float s2 = B[rr];
                #pragma unroll
                for (int k = 0; k < rr; k++) s2 = fmaf(-A[LT(rr, k)], B[k], s2);
                B[rr] = s2 * A[LT(rr, rr)];
            }
            // Back solve L^T w = z
            #pragma unroll
            for (int c = KD - 1; c >= 0; c--) {
                float s2 = B[c];
                #pragma unroll
                for (int k = c + 1; k < KD; k++) s2 = fmaf(-A[LT(k, c)], B[k], s2);
                B[c] = s2 * A[LT(c, c)];
            }
            #pragma unroll
            for (int k = 0; k < KD; k++) wbuf[r][k] = B[k];
        }
    }
    __syncthreads();

    // ================= Phase 3: emit (warp per row) =========================
    if (!active) return;
    const float* s = sh[warp];
    const float w0 = wbuf[warp][0], w1 = wbuf[warp][1], w2 = wbuf[warp][2],
                w3 = wbuf[warp][3], w4 = wbuf[warp][4], w5 = wbuf[warp][5],
                w6 = wbuf[warp][6];

    const size_t Ns = (size_t)N;
    float* coeffs = out;
    float* plog   = out + Ns * 3600;
    int*   phard  = (int*)(out + Ns * 3605);
    float* xhat   = out + Ns * 3606;

    // ---- coeffs: repeating [w1..w6] pattern over float4 (period 3) ----
    const float4 p0 = make_float4(w1, w2, w3, w4);
    const float4 p1 = make_float4(w5, w6, w1, w2);
    const float4 p2 = make_float4(w3, w4, w5, w6);
    const int m0 = lane % 3;
    const float4 q0 = (m0 == 0) ? p0 : ((m0 == 1) ? p1 : p2);  // c = 0
    const float4 q1 = (m0 == 0) ? p1 : ((m0 == 1) ? p2 : p0);  // c = 1
    const float4 q2 = (m0 == 0) ? p2 : ((m0 == 1) ? p0 : p1);  // c = 2

    float4* cv = (float4*)(coeffs + (size_t)row * 3600);
    {
        const float4 z4 = make_float4(0.f, 0.f, 0.f, 0.f);
        cv[lane] = (lane < 9) ? z4 : q0;
    }
    #pragma unroll
    for (int k = 1; k < 28; k++) {
        const int c = (2 * k) % 3;                // compile-time
        const float4 v = (c == 0) ? q0 : ((c == 1) ? q1 : q2);
        cv[lane + 32 * k] = v;
    }
    if (lane < 4) cv[lane + 896] = q2;           // tail, c = 2

    // ---- p_logits / p_hard: zeros ----
    if (lane < 5) plog[(size_t)row * 5 + lane] = 0.f;
    if (lane == 5) phard[row] = 0;

    // ---- x_hat: 0 for t<6, else w0 + sum w[k]*x[t-k] ----
    float4* hv = (float4*)(xhat + (size_t)row * SEQ);
    #pragma unroll
    for (int k = 0; k < 5; k++) {
        const int i = lane + k * 32;
        if (k < 4 || lane < 22) {                 // 150 = 4*32 + 22
            float4 v;
            float* vc = (float*)&v;
            const int t0 = i * 4;
            #pragma unroll
            for (int c = 0; c < 4; c++) {
                const int t = t0 + c;
                float p = 0.f;
                if (t >= PP) {
                    p = w0;
                    p = fmaf(w1, s[t - 1], p);
                    p = fmaf(w2, s[t - 2], p);
                    p = fmaf(w3, s[t - 3], p);
                    p = fmaf(w4, s[t - 4], p);
                    p = fmaf(w5, s[t - 5], p);
                    p = fmaf(w6, s[t - 6], p);
                }
                vc[c] = p;
            }
            hv[i] = v;
        }
    }
}

extern "C" void kernel_launch(void* const* d_in, const int* in_sizes, int n_in,
                              void* d_out, int out_size) {
    const float* x = (const float*)d_in[0];
    const int N = in_sizes[0] / SEQ;
    float* out = (float*)d_out;
    const int blocks = (N + NW - 1) / NW;
    ar_warp<<<blocks, NW * 32>>>(x, out, N);
}